// round 2
// baseline (speedup 1.0000x reference)
#include <cuda_runtime.h>
#include <stdint.h>

#define NROWS   131072
#define DIM     128
#define QSTAGES 4
#define KCB     1024
#define BETA    0.25

typedef unsigned long long u64;

// Scratch (allocation-free rule: __device__ globals)
__device__ float  g_resid[NROWS * DIM];        // 64 MB residual scratch
__device__ float  g_enorm[QSTAGES * KCB];      // ||E_k||^2, correctly rounded
__device__ double g_loss[QSTAGES];             // per-stage sum of r_new^2

// ---------------------------------------------------------------------------
// packed fp32x2 helpers (Blackwell sm_100+)
// ---------------------------------------------------------------------------
__device__ __forceinline__ u64 pack2f(float lo, float hi) {
    u64 r; asm("mov.b64 %0, {%1, %2};" : "=l"(r) : "f"(lo), "f"(hi)); return r;
}
__device__ __forceinline__ void unpack2f(u64 v, float& lo, float& hi) {
    asm("mov.b64 {%0, %1}, %2;" : "=f"(lo), "=f"(hi) : "l"(v));
}
__device__ __forceinline__ void ffma2(u64& d, u64 a, u64 b) {
    asm("fma.rn.f32x2 %0, %1, %2, %0;" : "+l"(d) : "l"(a), "l"(b));
}

__device__ __forceinline__ unsigned int fkey(float f) {
    unsigned int u = __float_as_uint(f);
    return (u & 0x80000000u) ? ~u : (u | 0x80000000u);   // monotone total order
}
__device__ __forceinline__ void top2(u64 k, u64& b0, u64& b1) {
    if (k < b0) { b1 = b0; b0 = k; }
    else if (k < b1) { b1 = k; }
}

// ---------------------------------------------------------------------------
// prep: codeword squared norms (double -> correctly-rounded float), zero loss
// ---------------------------------------------------------------------------
__global__ void rvq_prep_kernel(const float* __restrict__ cb) {
    if (blockIdx.x == 0 && threadIdx.x < QSTAGES) g_loss[threadIdx.x] = 0.0;
    int wid  = (blockIdx.x * blockDim.x + threadIdx.x) >> 5;
    int lane = threadIdx.x & 31;
    if (wid >= QSTAGES * KCB) return;
    const float* row = cb + (size_t)wid * DIM;
    double s = 0.0;
#pragma unroll
    for (int i = 0; i < 4; i++) {
        double v = (double)row[lane + i * 32];
        s = fma(v, v, s);
    }
#pragma unroll
    for (int off = 16; off; off >>= 1) s += __shfl_down_sync(0xffffffffu, s, off);
    if (lane == 0) g_enorm[wid] = (float)s;
}

// ---------------------------------------------------------------------------
// One RVQ stage. 256 threads, 128x128 tile, 8x8 microtile via fp32x2 FMA.
// Score replicates reference expression: s = ((rr - 2*dot) + ee).
// Top-2 candidates rescued with double-precision dot products.
// ---------------------------------------------------------------------------
template <int STAGE>
__global__ __launch_bounds__(256, 2)
void rvq_stage_kernel(const float* __restrict__ x,
                      const float* __restrict__ cbq,
                      float* __restrict__ out)
{
    const float* cb  = cbq + (size_t)STAGE * KCB * DIM;
    const float* rin = (STAGE == 0) ? x : (const float*)g_resid;

    __shared__ float As[8][132];
    __shared__ float Bs[8][132];
    __shared__ u64   RedA[128][17];
    __shared__ u64   RedB[128][17];
    __shared__ float rrS[128];
    __shared__ int   Ridx[128];
    __shared__ int   Ridx2[128];

    const int tid = threadIdx.x;
    const int m0  = blockIdx.x * 128;
    const int tx  = tid & 15;
    const int ty  = tid >> 4;
    const int lm  = tid >> 1;
    const int ld  = (tid & 1) * 4;

    // ---- pre-pass: rr per row (double, correctly rounded) ----
    {
        const int row = tid >> 1;
        const int h   = (tid & 1) * 64;
        const float* rv = rin + (size_t)(m0 + row) * DIM + h;
        double s = 0.0;
#pragma unroll
        for (int c = 0; c < 16; c++) {
            float4 v = *(const float4*)(rv + c * 4);
            s = fma((double)v.x, (double)v.x, s);
            s = fma((double)v.y, (double)v.y, s);
            s = fma((double)v.z, (double)v.z, s);
            s = fma((double)v.w, (double)v.w, s);
        }
        s += __shfl_xor_sync(0xffffffffu, s, 1);
        if ((tid & 1) == 0) rrS[row] = (float)s;
    }
    __syncthreads();

    float rrv[8];
#pragma unroll
    for (int i = 0; i < 8; i++) rrv[i] = rrS[ty * 8 + i];

    u64 best0 = 0xFFFFFFFFFFFFFFFFull, best1 = 0xFFFFFFFFFFFFFFFFull;

    const float* aBase = rin + (size_t)(m0 + lm) * DIM + ld;

    for (int nt = 0; nt < KCB / 128; nt++) {
        const int n0 = nt * 128;
        u64 acc2[4][8];
#pragma unroll
        for (int p = 0; p < 4; p++)
#pragma unroll
            for (int j = 0; j < 8; j++) acc2[p][j] = 0ull;

        const float* bBase = cb + (size_t)(n0 + lm) * DIM + ld;

        float4 areg = *(const float4*)(aBase);
        float4 breg = *(const float4*)(bBase);

#pragma unroll 1
        for (int ds = 0; ds < 16; ds++) {
            As[ld + 0][lm] = areg.x; As[ld + 1][lm] = areg.y;
            As[ld + 2][lm] = areg.z; As[ld + 3][lm] = areg.w;
            Bs[ld + 0][lm] = breg.x; Bs[ld + 1][lm] = breg.y;
            Bs[ld + 2][lm] = breg.z; Bs[ld + 3][lm] = breg.w;
            __syncthreads();
            if (ds < 15) {
                areg = *(const float4*)(aBase + (ds + 1) * 8);
                breg = *(const float4*)(bBase + (ds + 1) * 8);
            }
#pragma unroll
            for (int dd = 0; dd < 8; dd++) {
                const u64* a64 = reinterpret_cast<const u64*>(&As[dd][ty * 8]);
                u64 a2[4];
#pragma unroll
                for (int p = 0; p < 4; p++) a2[p] = a64[p];
                float b[8];
                *(float4*)(b)     = *(const float4*)&Bs[dd][tx * 8];
                *(float4*)(b + 4) = *(const float4*)&Bs[dd][tx * 8 + 4];
                u64 bb[8];
#pragma unroll
                for (int j = 0; j < 8; j++) bb[j] = pack2f(b[j], b[j]);
#pragma unroll
                for (int p = 0; p < 4; p++)
#pragma unroll
                    for (int j = 0; j < 8; j++)
                        ffma2(acc2[p][j], a2[p], bb[j]);
            }
            __syncthreads();
        }

        // scores replicate reference: s = (rr - 2*dot) + ee  (2*dot exact)
        float en[8];
#pragma unroll
        for (int j = 0; j < 8; j++) en[j] = __ldg(&g_enorm[STAGE * KCB + n0 + tx * 8 + j]);
#pragma unroll
        for (int p = 0; p < 4; p++) {
            const int r0 = 2 * p;
            u64 a0 = 0xFFFFFFFFFFFFFFFFull, a1 = 0xFFFFFFFFFFFFFFFFull;
            u64 c0 = 0xFFFFFFFFFFFFFFFFull, c1 = 0xFFFFFFFFFFFFFFFFull;
#pragma unroll
            for (int j = 0; j < 8; j++) {
                float dlo, dhi;
                unpack2f(acc2[p][j], dlo, dhi);
                float slo = (rrv[r0]     - 2.0f * dlo) + en[j];
                float shi = (rrv[r0 + 1] - 2.0f * dhi) + en[j];
                unsigned idx = (unsigned)(n0 + tx * 8 + j);
                top2(((u64)fkey(slo) << 32) | idx, a0, a1);
                top2(((u64)fkey(shi) << 32) | idx, c0, c1);
            }
            RedA[ty * 8 + r0][tx] = a0;     RedB[ty * 8 + r0][tx] = a1;
            RedA[ty * 8 + r0 + 1][tx] = c0; RedB[ty * 8 + r0 + 1][tx] = c1;
        }
        __syncthreads();
        if (tid < 128) {
#pragma unroll
            for (int t = 0; t < 16; t++) {
                top2(RedA[tid][t], best0, best1);
                top2(RedB[tid][t], best0, best1);
            }
        }
        __syncthreads();
    }

    if (tid < 128) {
        Ridx[tid]  = (int)(best0 & 0xFFFFFFFFull);
        Ridx2[tid] = (int)(best1 & 0xFFFFFFFFull);
    }
    __syncthreads();

    // ---- rescue + residual update + loss ----
    const int row = tid >> 1;
    const int h   = (tid & 1) * 64;
    const int i1  = Ridx[row];
    const int i2  = Ridx2[row];
    const float* rv = rin + (size_t)(m0 + row) * DIM + h;
    const float* e1 = cb + (size_t)i1 * DIM + h;
    const float* e2 = cb + (size_t)i2 * DIM + h;

    double d1 = 0.0, d2 = 0.0;
#pragma unroll
    for (int c = 0; c < 16; c++) {
        float4 r4 = *(const float4*)(rv + c * 4);
        float4 q1 = *(const float4*)(e1 + c * 4);
        float4 q2 = *(const float4*)(e2 + c * 4);
        d1 = fma((double)r4.x, (double)q1.x, d1);
        d1 = fma((double)r4.y, (double)q1.y, d1);
        d1 = fma((double)r4.z, (double)q1.z, d1);
        d1 = fma((double)r4.w, (double)q1.w, d1);
        d2 = fma((double)r4.x, (double)q2.x, d2);
        d2 = fma((double)r4.y, (double)q2.y, d2);
        d2 = fma((double)r4.z, (double)q2.z, d2);
        d2 = fma((double)r4.w, (double)q2.w, d2);
    }
    d1 += __shfl_xor_sync(0xffffffffu, d1, 1);
    d2 += __shfl_xor_sync(0xffffffffu, d2, 1);

    const float rr = rrS[row];
    const float s1 = (rr - 2.0f * (float)d1) + __ldg(&g_enorm[STAGE * KCB + i1]);
    const float s2 = (rr - 2.0f * (float)d2) + __ldg(&g_enorm[STAGE * KCB + i2]);
    int cidx;
    if (s1 < s2)      cidx = i1;
    else if (s2 < s1) cidx = i2;
    else              cidx = (i1 < i2) ? i1 : i2;

    if ((tid & 1) == 0)
        out[(size_t)NROWS * DIM + 1 + (size_t)(m0 + row) * QSTAGES + STAGE] = (float)cidx;

    const float* qv = cb + (size_t)cidx * DIM + h;
    double lsum = 0.0;
#pragma unroll
    for (int c = 0; c < 16; c++) {
        float4 q = *(const float4*)(qv + c * 4);
        float4 r = *(const float4*)(rv + c * 4);
        float4 rn;
        rn.x = r.x - q.x; rn.y = r.y - q.y; rn.z = r.z - q.z; rn.w = r.w - q.w;
        lsum += (double)rn.x * rn.x + (double)rn.y * rn.y +
                (double)rn.z * rn.z + (double)rn.w * rn.w;
        if (STAGE < QSTAGES - 1) {
            *(float4*)(g_resid + (size_t)(m0 + row) * DIM + h + c * 4) = rn;
        } else {
            const float4 xx = *(const float4*)(x + (size_t)(m0 + row) * DIM + h + c * 4);
            float4 xq;
            xq.x = xx.x - rn.x; xq.y = xx.y - rn.y;
            xq.z = xx.z - rn.z; xq.w = xx.w - rn.w;
            *(float4*)(out + (size_t)(m0 + row) * DIM + h + c * 4) = xq;
        }
    }
#pragma unroll
    for (int off = 16; off; off >>= 1) lsum += __shfl_down_sync(0xffffffffu, lsum, off);
    if ((tid & 31) == 0) atomicAdd(&g_loss[STAGE], lsum);
}

// ---------------------------------------------------------------------------
__global__ void rvq_finalize_kernel(float* __restrict__ out) {
    if (threadIdx.x == 0) {
        double s = 0.0;
        for (int i = 0; i < QSTAGES; i++) s += g_loss[i];
        double mean = (1.0 + BETA) * s / ((double)NROWS * DIM) / (double)QSTAGES;
        out[(size_t)NROWS * DIM] = (float)mean;
    }
}

extern "C" void kernel_launch(void* const* d_in, const int* in_sizes, int n_in,
                              void* d_out, int out_size) {
    const float* x  = (const float*)d_in[0];
    const float* cb = (const float*)d_in[1];
    if (n_in >= 2 && in_sizes[0] == QSTAGES * KCB * DIM && in_sizes[1] == NROWS * DIM) {
        x  = (const float*)d_in[1];
        cb = (const float*)d_in[0];
    }
    float* out = (float*)d_out;

    rvq_prep_kernel<<<512, 256>>>(cb);
    rvq_stage_kernel<0><<<NROWS / 128, 256>>>(x, cb, out);
    rvq_stage_kernel<1><<<NROWS / 128, 256>>>(x, cb, out);
    rvq_stage_kernel<2><<<NROWS / 128, 256>>>(x, cb, out);
    rvq_stage_kernel<3><<<NROWS / 128, 256>>>(x, cb, out);
    rvq_finalize_kernel<<<1, 32>>>(out);
}